// round 2
// baseline (speedup 1.0000x reference)
#include <cuda_runtime.h>
#include <cstdint>

#define NCLS   10
#define NBINS  11          // 10 classes + dummy bin for mask==0
#define BLOCK  256
#define NGRID  (152 * 8)   // GB300: 152 SMs, 8 blocks/SM

// Per-block partials (col-major per class for coalesced final reduce) + ticket.
__device__ float2       g_part[NCLS][NGRID];
__device__ unsigned int g_ticket = 0;

// One element -> this thread's private smem bin row.
// bins layout: [NBINS][BLOCK] float2; row stride 2048 B => conflict-free LDS/STS.64.
__device__ __forceinline__ void acc_one(float ov, float tv, int mv, float2* row_tid) {
    float e  = ov - tv;
    float sq = e * e;
    int cls  = (int)tv;                 // targets are exact small ints
    int key  = (mv == 1) ? cls : NCLS;  // invalid -> dummy bin
    float2* p = row_tid + key * BLOCK;

    unsigned long long v = *reinterpret_cast<unsigned long long*>(p);
    unsigned long long inc;
    asm("mov.b64 %0, {%1, %2};" : "=l"(inc) : "f"(sq), "f"(1.0f));
    asm("add.rn.f32x2 %0, %1, %2;" : "=l"(v) : "l"(v), "l"(inc));
    *reinterpret_cast<unsigned long long*>(p) = v;
}

__global__ __launch_bounds__(BLOCK) void loss_k(
    const float* __restrict__ outs,
    const float* __restrict__ tgts,
    const int*   __restrict__ mask,
    int n, float* __restrict__ out, int out_size)
{
    __shared__ float2 bins[NBINS][BLOCK];
    __shared__ unsigned int s_ticket;
    const int tid = threadIdx.x;

    #pragma unroll
    for (int c = 0; c < NBINS; c++) bins[c][tid] = make_float2(0.0f, 0.0f);
    __syncthreads();

    float2* row_tid = &bins[0][tid];

    const int n4 = n >> 2;
    const float4* __restrict__ o4 = reinterpret_cast<const float4*>(outs);
    const float4* __restrict__ t4 = reinterpret_cast<const float4*>(tgts);
    const int4*   __restrict__ m4 = reinterpret_cast<const int4*>(mask);

    const int stride = NGRID * BLOCK;
    for (int i = blockIdx.x * BLOCK + tid; i < n4; i += stride) {
        float4 ov = o4[i];
        float4 tv = t4[i];
        int4   mv = m4[i];
        acc_one(ov.x, tv.x, mv.x, row_tid);
        acc_one(ov.y, tv.y, mv.y, row_tid);
        acc_one(ov.z, tv.z, mv.z, row_tid);
        acc_one(ov.w, tv.w, mv.w, row_tid);
    }
    if (blockIdx.x == 0) {          // tail (n % 4)
        int i = (n4 << 2) + tid;
        if (i < n) acc_one(outs[i], tgts[i], mask[i], row_tid);
    }
    __syncthreads();

    // Block tree-reduction per class row (dummy bin dropped).
    for (int s = BLOCK / 2; s > 0; s >>= 1) {
        if (tid < s) {
            #pragma unroll
            for (int c = 0; c < NCLS; c++) {
                float2 a = bins[c][tid];
                float2 b = bins[c][tid + s];
                bins[c][tid] = make_float2(a.x + b.x, a.y + b.y);
            }
        }
        __syncthreads();
    }

    if (tid < NCLS) g_part[tid][blockIdx.x] = bins[tid][0];
    __threadfence();
    __syncthreads();
    if (tid == 0) s_ticket = atomicAdd(&g_ticket, 1u);
    __syncthreads();

    if (s_ticket != (unsigned)(gridDim.x - 1)) return;

    // ---- last block: reduce partials, finalize, write output ----
    __threadfence();

    float2 acc[NCLS];
    #pragma unroll
    for (int c = 0; c < NCLS; c++) acc[c] = make_float2(0.0f, 0.0f);
    for (int j = tid; j < NGRID; j += BLOCK) {
        #pragma unroll
        for (int c = 0; c < NCLS; c++) {
            float2 p = g_part[c][j];
            acc[c].x += p.x;
            acc[c].y += p.y;
        }
    }
    __syncthreads();   // smem bins reuse
    #pragma unroll
    for (int c = 0; c < NCLS; c++) bins[c][tid] = acc[c];
    __syncthreads();

    for (int s = BLOCK / 2; s > 0; s >>= 1) {
        if (tid < s) {
            #pragma unroll
            for (int c = 0; c < NCLS; c++) {
                float2 a = bins[c][tid];
                float2 b = bins[c][tid + s];
                bins[c][tid] = make_float2(a.x + b.x, a.y + b.y);
            }
        }
        __syncthreads();
    }

    __shared__ float le[NCLS];
    if (tid < NCLS) {
        float s_ = bins[tid][0].x;
        float n_ = bins[tid][0].y;
        le[tid] = (n_ > 0.0f) ? (s_ / fmaxf(n_, 1.0f)) : 0.0f;
    }
    __syncthreads();

    // out poisoned 0xAA: every slot written exactly once by a distinct thread.
    if (tid == 0) {
        float loss = 0.0f;
        #pragma unroll
        for (int c = 0; c < NCLS; c++) loss += 0.1f * le[c];
        out[0] = loss;
        g_ticket = 0;   // reset for next graph replay (kernel-boundary ordered)
    } else if (tid >= 1 && tid <= NCLS) {
        out[tid] = le[tid - 1];                        // loss_each
    } else if (tid >= NCLS + 1 && tid <= 2 * NCLS) {
        out[tid] = bins[tid - NCLS - 1][0].y;          // class_n
    } else if (tid < out_size) {
        out[tid] = 0.0f;                               // any padding slots
    }
}

extern "C" void kernel_launch(void* const* d_in, const int* in_sizes, int n_in,
                              void* d_out, int out_size) {
    const float* outs = (const float*)d_in[0];
    const float* tgts = (const float*)d_in[1];
    const int*   mask = (const int*)d_in[2];
    float* out = (float*)d_out;
    int n = in_sizes[0];

    loss_k<<<NGRID, BLOCK>>>(outs, tgts, mask, n, out, out_size);
}

// round 3
// speedup vs baseline: 1.1164x; 1.1164x over previous
#include <cuda_runtime.h>
#include <cstdint>

#define NCLS   10
#define NBINS  11              // 10 classes + dummy bin for mask==0
#define BLOCK  256
#define NGRID  (152 * 5)       // 5 blocks/SM @ 45KB smem -> exactly one wave

typedef unsigned long long ull;

__device__ float2       g_part[NCLS][NGRID];
__device__ unsigned int g_ticket = 0;

// Two elements into two INDEPENDENT bin sets; the two LDS latencies overlap.
__device__ __forceinline__ void acc2(float o0, float t0, int m0, float2* rA,
                                     float o1, float t1, int m1, float2* rB) {
    float e0 = o0 - t0, e1 = o1 - t1;
    float s0 = e0 * e0, s1 = e1 * e1;
    int k0 = (m0 == 1) ? (int)t0 : NCLS;
    int k1 = (m1 == 1) ? (int)t1 : NCLS;
    ull* pA = reinterpret_cast<ull*>(rA + k0 * BLOCK);
    ull* pB = reinterpret_cast<ull*>(rB + k1 * BLOCK);
    ull vA = *pA;                      // independent loads -> overlap
    ull vB = *pB;
    ull iA, iB;
    asm("mov.b64 %0, {%1, %2};" : "=l"(iA) : "f"(s0), "f"(1.0f));
    asm("mov.b64 %0, {%1, %2};" : "=l"(iB) : "f"(s1), "f"(1.0f));
    asm("add.rn.f32x2 %0, %1, %2;" : "=l"(vA) : "l"(vA), "l"(iA));
    asm("add.rn.f32x2 %0, %1, %2;" : "=l"(vB) : "l"(vB), "l"(iB));
    *pA = vA;
    *pB = vB;
}

__global__ __launch_bounds__(BLOCK) void loss_k(
    const float* __restrict__ outs,
    const float* __restrict__ tgts,
    const int*   __restrict__ mask,
    int n, float* __restrict__ out, int out_size)
{
    // Distinct shared objects => provably non-aliasing => parallel chains.
    __shared__ float2 binsA[NBINS][BLOCK];
    __shared__ float2 binsB[NBINS][BLOCK];
    __shared__ float  le[NCLS];
    __shared__ unsigned int s_ticket;
    const int tid = threadIdx.x;

    #pragma unroll
    for (int c = 0; c < NBINS; c++) {
        binsA[c][tid] = make_float2(0.0f, 0.0f);
        binsB[c][tid] = make_float2(0.0f, 0.0f);
    }
    __syncthreads();

    float2* rA = &binsA[0][tid];
    float2* rB = &binsB[0][tid];

    const int n4 = n >> 2;
    const float4* __restrict__ o4 = reinterpret_cast<const float4*>(outs);
    const float4* __restrict__ t4 = reinterpret_cast<const float4*>(tgts);
    const int4*   __restrict__ m4 = reinterpret_cast<const int4*>(mask);

    const int stride = NGRID * BLOCK;
    int i = blockIdx.x * BLOCK + tid;

    // unroll x2: 6 LDG.128 front-batched per iteration (MLP ~6/warp)
    for (; i + stride < n4; i += 2 * stride) {
        float4 ov0 = o4[i];
        float4 ov1 = o4[i + stride];
        float4 tv0 = t4[i];
        float4 tv1 = t4[i + stride];
        int4   mv0 = m4[i];
        int4   mv1 = m4[i + stride];
        acc2(ov0.x, tv0.x, mv0.x, rA,  ov0.y, tv0.y, mv0.y, rB);
        acc2(ov0.z, tv0.z, mv0.z, rA,  ov0.w, tv0.w, mv0.w, rB);
        acc2(ov1.x, tv1.x, mv1.x, rA,  ov1.y, tv1.y, mv1.y, rB);
        acc2(ov1.z, tv1.z, mv1.z, rA,  ov1.w, tv1.w, mv1.w, rB);
    }
    if (i < n4) {                       // leftover float4 (at most one)
        float4 ov = o4[i];
        float4 tv = t4[i];
        int4   mv = m4[i];
        acc2(ov.x, tv.x, mv.x, rA,  ov.y, tv.y, mv.y, rB);
        acc2(ov.z, tv.z, mv.z, rA,  ov.w, tv.w, mv.w, rB);
    }
    if (blockIdx.x == 0) {              // scalar tail (n % 4)
        int j = (n4 << 2) + tid;
        if (j < n) {
            float e = outs[j] - tgts[j];
            int key = (mask[j] == 1) ? (int)tgts[j] : NCLS;
            float2 v = *(rA + key * BLOCK);
            v.x += e * e; v.y += 1.0f;
            *(rA + key * BLOCK) = v;
        }
    }
    __syncthreads();

    // Merge B into A, then tree-reduce (dummy bin dropped).
    #pragma unroll
    for (int c = 0; c < NCLS; c++) {
        float2 a = binsA[c][tid];
        float2 b = binsB[c][tid];
        binsA[c][tid] = make_float2(a.x + b.x, a.y + b.y);
    }
    __syncthreads();
    for (int s = BLOCK / 2; s > 0; s >>= 1) {
        if (tid < s) {
            #pragma unroll
            for (int c = 0; c < NCLS; c++) {
                float2 a = binsA[c][tid];
                float2 b = binsA[c][tid + s];
                binsA[c][tid] = make_float2(a.x + b.x, a.y + b.y);
            }
        }
        __syncthreads();
    }

    if (tid < NCLS) g_part[tid][blockIdx.x] = binsA[tid][0];
    __threadfence();
    __syncthreads();
    if (tid == 0) s_ticket = atomicAdd(&g_ticket, 1u);
    __syncthreads();
    if (s_ticket != (unsigned)(gridDim.x - 1)) return;

    // ---- last block: reduce partials, finalize, write output ----
    __threadfence();

    float2 acc[NCLS];
    #pragma unroll
    for (int c = 0; c < NCLS; c++) acc[c] = make_float2(0.0f, 0.0f);
    for (int j = tid; j < NGRID; j += BLOCK) {
        #pragma unroll
        for (int c = 0; c < NCLS; c++) {
            float2 p = g_part[c][j];
            acc[c].x += p.x;
            acc[c].y += p.y;
        }
    }
    __syncthreads();
    #pragma unroll
    for (int c = 0; c < NCLS; c++) binsA[c][tid] = acc[c];
    __syncthreads();
    for (int s = BLOCK / 2; s > 0; s >>= 1) {
        if (tid < s) {
            #pragma unroll
            for (int c = 0; c < NCLS; c++) {
                float2 a = binsA[c][tid];
                float2 b = binsA[c][tid + s];
                binsA[c][tid] = make_float2(a.x + b.x, a.y + b.y);
            }
        }
        __syncthreads();
    }

    if (tid < NCLS) {
        float s_ = binsA[tid][0].x;
        float n_ = binsA[tid][0].y;
        le[tid] = (n_ > 0.0f) ? (s_ / fmaxf(n_, 1.0f)) : 0.0f;
    }
    __syncthreads();

    if (tid == 0) {
        float loss = 0.0f;
        #pragma unroll
        for (int c = 0; c < NCLS; c++) loss += 0.1f * le[c];
        out[0] = loss;
        g_ticket = 0;    // reset for graph replay determinism
    } else if (tid >= 1 && tid <= NCLS) {
        out[tid] = le[tid - 1];                      // loss_each
    } else if (tid >= NCLS + 1 && tid <= 2 * NCLS) {
        out[tid] = binsA[tid - NCLS - 1][0].y;       // class_n
    } else if (tid < out_size) {
        out[tid] = 0.0f;
    }
}

extern "C" void kernel_launch(void* const* d_in, const int* in_sizes, int n_in,
                              void* d_out, int out_size) {
    const float* outs = (const float*)d_in[0];
    const float* tgts = (const float*)d_in[1];
    const int*   mask = (const int*)d_in[2];
    float* out = (float*)d_out;
    int n = in_sizes[0];

    loss_k<<<NGRID, BLOCK>>>(outs, tgts, mask, n, out, out_size);
}

// round 4
// speedup vs baseline: 1.1323x; 1.0142x over previous
#include <cuda_runtime.h>
#include <cstdint>

#define NCLS   10
#define BLOCK  256
#define NGRID  (152 * 4)     // 4 blocks/SM @ <=64 regs -> exactly one wave
#define NWARPS (BLOCK / 32)

typedef unsigned long long ull;

__device__ float2       g_part[NGRID][NCLS];
__device__ unsigned int g_ticket = 0;

// One element -> 10 register accumulators via predicated packed f32x2 adds.
// acc[c] holds {sum, count} as a 64-bit register pair.
__device__ __forceinline__ void acc_el(float o, float t, int m, ull* acc) {
    float e  = o - t;
    float sq = e * e;
    int  key = (m == 1) ? (int)t : NCLS;   // dummy key 10 matches no class
    ull inc;
    asm("mov.b64 %0, {%1, %2};" : "=l"(inc) : "f"(sq), "f"(1.0f));
    #pragma unroll
    for (int c = 0; c < NCLS; c++) {
        asm("{ .reg .pred p; setp.eq.s32 p, %1, %2; @p add.rn.f32x2 %0, %0, %3; }"
            : "+l"(acc[c]) : "r"(key), "r"(c), "l"(inc));
    }
}

__global__ __launch_bounds__(BLOCK, 4) void loss_k(
    const float* __restrict__ outs,
    const float* __restrict__ tgts,
    const int*   __restrict__ mask,
    int n, float* __restrict__ out, int out_size)
{
    __shared__ float2 s_warp[NWARPS][NCLS];
    __shared__ float  le[NCLS];
    __shared__ unsigned int s_ticket;
    const int tid  = threadIdx.x;
    const int lane = tid & 31;
    const int wid  = tid >> 5;

    ull acc[NCLS];
    #pragma unroll
    for (int c = 0; c < NCLS; c++) acc[c] = 0ull;   // {0.0f, 0.0f}

    const int n4 = n >> 2;
    const float4* __restrict__ o4 = reinterpret_cast<const float4*>(outs);
    const float4* __restrict__ t4 = reinterpret_cast<const float4*>(tgts);
    const int4*   __restrict__ m4 = reinterpret_cast<const int4*>(mask);

    const int stride = NGRID * BLOCK;
    int i = blockIdx.x * BLOCK + tid;

    // unroll x2: 6 front-batched LDG.128 per iteration
    for (; i + stride < n4; i += 2 * stride) {
        float4 ov0 = o4[i];
        float4 ov1 = o4[i + stride];
        float4 tv0 = t4[i];
        float4 tv1 = t4[i + stride];
        int4   mv0 = m4[i];
        int4   mv1 = m4[i + stride];
        acc_el(ov0.x, tv0.x, mv0.x, acc);
        acc_el(ov0.y, tv0.y, mv0.y, acc);
        acc_el(ov0.z, tv0.z, mv0.z, acc);
        acc_el(ov0.w, tv0.w, mv0.w, acc);
        acc_el(ov1.x, tv1.x, mv1.x, acc);
        acc_el(ov1.y, tv1.y, mv1.y, acc);
        acc_el(ov1.z, tv1.z, mv1.z, acc);
        acc_el(ov1.w, tv1.w, mv1.w, acc);
    }
    if (i < n4) {
        float4 ov = o4[i];
        float4 tv = t4[i];
        int4   mv = m4[i];
        acc_el(ov.x, tv.x, mv.x, acc);
        acc_el(ov.y, tv.y, mv.y, acc);
        acc_el(ov.z, tv.z, mv.z, acc);
        acc_el(ov.w, tv.w, mv.w, acc);
    }
    if (blockIdx.x == 0) {               // scalar tail (n % 4)
        int j = (n4 << 2) + tid;
        if (j < n) acc_el(outs[j], tgts[j], mask[j], acc);
    }

    // ---- warp shuffle reduction (float2 packed in ull) ----
    #pragma unroll
    for (int off = 16; off > 0; off >>= 1) {
        #pragma unroll
        for (int c = 0; c < NCLS; c++) {
            ull other = __shfl_down_sync(0xffffffffu, acc[c], off);
            ull r;
            asm("add.rn.f32x2 %0, %1, %2;" : "=l"(r) : "l"(acc[c]), "l"(other));
            acc[c] = r;
        }
    }
    if (lane == 0) {
        #pragma unroll
        for (int c = 0; c < NCLS; c++) {
            float2 v;
            asm("mov.b64 {%0, %1}, %2;" : "=f"(v.x), "=f"(v.y) : "l"(acc[c]));
            s_warp[wid][c] = v;
        }
    }
    __syncthreads();

    // ---- per-block partial: threads 0..9 combine the 8 warp rows ----
    if (tid < NCLS) {
        float2 p = make_float2(0.0f, 0.0f);
        #pragma unroll
        for (int w = 0; w < NWARPS; w++) {
            float2 v = s_warp[w][tid];
            p.x += v.x; p.y += v.y;
        }
        g_part[blockIdx.x][tid] = p;
    }
    __threadfence();
    __syncthreads();
    if (tid == 0) s_ticket = atomicAdd(&g_ticket, 1u);
    __syncthreads();
    if (s_ticket != (unsigned)(gridDim.x - 1)) return;

    // ---- last block: reduce 608 partials, finalize, write output ----
    __threadfence();

    float2 racc[NCLS];
    #pragma unroll
    for (int c = 0; c < NCLS; c++) racc[c] = make_float2(0.0f, 0.0f);
    for (int j = tid; j < NGRID; j += BLOCK) {
        #pragma unroll
        for (int c = 0; c < NCLS; c++) {
            float2 p = g_part[j][c];
            racc[c].x += p.x;
            racc[c].y += p.y;
        }
    }
    #pragma unroll
    for (int off = 16; off > 0; off >>= 1) {
        #pragma unroll
        for (int c = 0; c < NCLS; c++) {
            racc[c].x += __shfl_down_sync(0xffffffffu, racc[c].x, off);
            racc[c].y += __shfl_down_sync(0xffffffffu, racc[c].y, off);
        }
    }
    if (lane == 0) {
        #pragma unroll
        for (int c = 0; c < NCLS; c++) s_warp[wid][c] = racc[c];
    }
    __syncthreads();

    if (tid < NCLS) {
        float2 tot = make_float2(0.0f, 0.0f);
        #pragma unroll
        for (int w = 0; w < NWARPS; w++) {
            float2 v = s_warp[w][tid];
            tot.x += v.x; tot.y += v.y;
        }
        s_warp[0][tid] = tot;
        le[tid] = (tot.y > 0.0f) ? (tot.x / fmaxf(tot.y, 1.0f)) : 0.0f;
    }
    __syncthreads();

    if (tid == 0) {
        float loss = 0.0f;
        #pragma unroll
        for (int c = 0; c < NCLS; c++) loss += 0.1f * le[c];
        out[0] = loss;
        g_ticket = 0;    // reset for graph replay determinism
    } else if (tid >= 1 && tid <= NCLS) {
        out[tid] = le[tid - 1];                  // loss_each
    } else if (tid >= NCLS + 1 && tid <= 2 * NCLS) {
        out[tid] = s_warp[0][tid - NCLS - 1].y;  // class_n
    } else if (tid < out_size) {
        out[tid] = 0.0f;
    }
}

extern "C" void kernel_launch(void* const* d_in, const int* in_sizes, int n_in,
                              void* d_out, int out_size) {
    const float* outs = (const float*)d_in[0];
    const float* tgts = (const float*)d_in[1];
    const int*   mask = (const int*)d_in[2];
    float* out = (float*)d_out;
    int n = in_sizes[0];

    loss_k<<<NGRID, BLOCK>>>(outs, tgts, mask, n, out, out_size);
}